// round 3
// baseline (speedup 1.0000x reference)
#include <cuda_runtime.h>
#include <math.h>

#define BB 1024
#define TT 80
#define EE 100
#define EP 112      // E padded to multiple of 4 floats
#define UU 256
#define HS (BB*UU)

// ---------------- device scratch (no allocations allowed) ----------------
__device__ float g_X[(size_t)TT * BB * EP];   // [t][b][e], zero-padded e>=100
__device__ float g_h1[2][HS];
__device__ float g_c1[HS];
__device__ float g_h2[2][HS];
__device__ float g_c2[HS];

// ---------------- f32x2 packed helpers ----------------
__device__ __forceinline__ unsigned long long pack2(float lo, float hi) {
    unsigned long long r;
    asm("mov.b64 %0, {%1, %2};" : "=l"(r) : "f"(lo), "f"(hi));
    return r;
}
__device__ __forceinline__ void ffma2(unsigned long long& acc,
                                      unsigned long long a, unsigned long long w) {
    asm("fma.rn.f32x2 %0, %1, %2, %0;" : "+l"(acc) : "l"(a), "l"(w));
}
__device__ __forceinline__ float2 unpack2(unsigned long long v) {
    float2 r;
    asm("mov.b64 {%0, %1}, %2;" : "=f"(r.x), "=f"(r.y) : "l"(v));
    return r;
}

// ---------------- init: embedding gather + zero states ----------------
__global__ void init_kernel(const int* __restrict__ tokens,
                            const float* __restrict__ emb) {
    int idx = blockIdx.x * 256 + threadIdx.x;
    if (idx < TT * BB * EP) {
        int e  = idx % EP;
        int tb = idx / EP;
        int b  = tb % BB;
        int t  = tb / BB;
        float v = 0.0f;
        if (e < EE) {
            int tok = tokens[b * TT + t];
            v = emb[(size_t)tok * EE + e];
        }
        g_X[idx] = v;
    }
    if (idx < HS) {
        g_h1[0][idx] = 0.0f;
        g_c1[idx]    = 0.0f;
        g_h2[0][idx] = 0.0f;
        g_c2[idx]    = 0.0f;
    }
}

// ---------------- one LSTM layer tile: 64 batch x 16 units x 4 gates ----------------
// Double-buffered smem, f32x2 FMAs, full cell update in epilogue.
__device__ __forceinline__ void lstm_tile(
    const float* __restrict__ h_in, float* __restrict__ h_out,
    float* __restrict__ c_st, const float* __restrict__ x,
    const float* __restrict__ Wf, const float* __restrict__ Wi,
    const float* __restrict__ Wc, const float* __restrict__ Wo,
    const float* __restrict__ bf, const float* __restrict__ bi,
    const float* __restrict__ bc, const float* __restrict__ bo,
    int DX, int Dvalid, int NK,
    float (*As)[16][72], float (*Ws)[16][72]) {

    const int tid = threadIdx.x;
    const int b0  = blockIdx.x * 64;
    const int n0  = blockIdx.y * 16;

    const int tm = tid >> 4;          // 0..15 -> 4 batch rows each
    const int tn = tid & 15;          // unit within tile

    // A loader: thread loads float4 = 4 consecutive k for one batch row
    const int lb  = tid & 63;
    const int lak = tid >> 6;         // 0..3 -> k offset lak*4
    // W loader: thread loads float4 = 4 consecutive units of one gate, one k-row
    const int lg  = tid & 3;
    const int lk  = (tid >> 2) & 15;
    const int lj  = tid >> 6;         // 0..3 -> units lj*4..+3
    const float* Wg = (lg == 0) ? Wf : ((lg == 1) ? Wi : ((lg == 2) ? Wc : Wo));

    float4 ra, rw;

    auto load_g = [&](int kt) {
        int k = kt * 16 + lak * 4;
        const float* src = (k < UU)
            ? (h_in + (size_t)(b0 + lb) * UU + k)
            : (x    + (size_t)(b0 + lb) * DX + (k - UU));
        ra = *(const float4*)src;
        int row = kt * 16 + lk;
        if (row >= Dvalid) row = Dvalid - 1;   // pad rows multiply zeros in A
        rw = *(const float4*)(Wg + (size_t)row * UU + n0 + lj * 4);
    };
    auto store_s = [&](int buf) {
        As[buf][lak * 4 + 0][lb] = ra.x;
        As[buf][lak * 4 + 1][lb] = ra.y;
        As[buf][lak * 4 + 2][lb] = ra.z;
        As[buf][lak * 4 + 3][lb] = ra.w;
        Ws[buf][lk][(lj * 4 + 0) * 4 + lg] = rw.x;   // interleave gates: [n*4+g]
        Ws[buf][lk][(lj * 4 + 1) * 4 + lg] = rw.y;
        Ws[buf][lk][(lj * 4 + 2) * 4 + lg] = rw.z;
        Ws[buf][lk][(lj * 4 + 3) * 4 + lg] = rw.w;
    };

    unsigned long long aFI[4] = {0ull, 0ull, 0ull, 0ull};  // (f,i) pairs, 4 batch rows
    unsigned long long aCO[4] = {0ull, 0ull, 0ull, 0ull};  // (c,o) pairs

    load_g(0);
    store_s(0);
    __syncthreads();

    int buf = 0;
    for (int kt = 0; kt < NK; kt++) {
        const bool more = (kt + 1 < NK);
        if (more) load_g(kt + 1);
#pragma unroll
        for (int kk = 0; kk < 16; kk++) {
            float4 a = *(const float4*)&As[buf][kk][tm * 4];
            ulonglong2 w = *(const ulonglong2*)&Ws[buf][kk][tn * 4]; // {(f,i),(c,o)}
            unsigned long long a0 = pack2(a.x, a.x);
            unsigned long long a1 = pack2(a.y, a.y);
            unsigned long long a2 = pack2(a.z, a.z);
            unsigned long long a3 = pack2(a.w, a.w);
            ffma2(aFI[0], a0, w.x);  ffma2(aCO[0], a0, w.y);
            ffma2(aFI[1], a1, w.x);  ffma2(aCO[1], a1, w.y);
            ffma2(aFI[2], a2, w.x);  ffma2(aCO[2], a2, w.y);
            ffma2(aFI[3], a3, w.x);  ffma2(aCO[3], a3, w.y);
        }
        if (more) store_s(buf ^ 1);
        buf ^= 1;
        __syncthreads();
    }

    // ---- LSTM cell epilogue ----
    const int u = n0 + tn;
    const float bfv = bf[u], biv = bi[u], bcv = bc[u], bov = bo[u];
#pragma unroll
    for (int mi = 0; mi < 4; mi++) {
        const int b = b0 + tm * 4 + mi;
        float2 fi = unpack2(aFI[mi]);
        float2 co = unpack2(aCO[mi]);
        float sf = 1.0f / (1.0f + expf(-(fi.x + bfv)));
        float si = 1.0f / (1.0f + expf(-(fi.y + biv)));
        float ct = tanhf(co.x + bcv);
        float so = 1.0f / (1.0f + expf(-(co.y + bov)));
        float cn = sf * c_st[(size_t)b * UU + u] + si * ct;
        c_st[(size_t)b * UU + u]  = cn;
        h_out[(size_t)b * UU + u] = so * tanhf(cn);
    }
}

// ---------------- fused step: z=0 -> layer2(step k-1), z=1 -> layer1(step k) ----------------
__global__ __launch_bounds__(256)
void fused_step(
    int do1, const float* __restrict__ h1i, float* __restrict__ h1o,
    float* __restrict__ c1, const float* __restrict__ x1,
    const float* __restrict__ wf1, const float* __restrict__ wi1,
    const float* __restrict__ wc1, const float* __restrict__ wo1,
    const float* __restrict__ bf1, const float* __restrict__ bi1,
    const float* __restrict__ bc1, const float* __restrict__ bo1,
    int do2, const float* __restrict__ h2i, float* __restrict__ h2o,
    float* __restrict__ c2, const float* __restrict__ x2,
    const float* __restrict__ wf2, const float* __restrict__ wi2,
    const float* __restrict__ wc2, const float* __restrict__ wo2,
    const float* __restrict__ bf2, const float* __restrict__ bi2,
    const float* __restrict__ bc2, const float* __restrict__ bo2) {

    __shared__ float As[2][16][72];
    __shared__ float Ws[2][16][72];

    if (blockIdx.z == 1) {
        if (!do1) return;
        lstm_tile(h1i, h1o, c1, x1, wf1, wi1, wc1, wo1, bf1, bi1, bc1, bo1,
                  EP, UU + EE, (UU + EP) / 16, As, Ws);
    } else {
        if (!do2) return;
        lstm_tile(h2i, h2o, c2, x2, wf2, wi2, wc2, wo2, bf2, bi2, bc2, bo2,
                  UU, UU + UU, (UU + UU) / 16, As, Ws);
    }
}

// ---------------- output head ----------------
__global__ void final_kernel(const float* __restrict__ h2,
                             const float* __restrict__ w_out,
                             const float* __restrict__ b_out,
                             float* __restrict__ out) {
    int b    = blockIdx.x * 8 + (threadIdx.x >> 5);
    int lane = threadIdx.x & 31;
    float s = 0.0f;
#pragma unroll
    for (int u = lane; u < UU; u += 32) s += h2[b * UU + u] * w_out[u];
#pragma unroll
    for (int off = 16; off; off >>= 1) s += __shfl_xor_sync(0xFFFFFFFFu, s, off);
    if (lane == 0) out[b] = 1.0f / (1.0f + expf(-(s + b_out[0])));
}

// ---------------- launch ----------------
extern "C" void kernel_launch(void* const* d_in, const int* in_sizes, int n_in,
                              void* d_out, int out_size) {
    const int*   tokens = (const int*)d_in[0];
    const float* emb    = (const float*)d_in[1];
    const float* wf1 = (const float*)d_in[2];  const float* bf1 = (const float*)d_in[3];
    const float* wi1 = (const float*)d_in[4];  const float* bi1 = (const float*)d_in[5];
    const float* wc1 = (const float*)d_in[6];  const float* bc1 = (const float*)d_in[7];
    const float* wo1 = (const float*)d_in[8];  const float* bo1 = (const float*)d_in[9];
    const float* wf2 = (const float*)d_in[10]; const float* bf2 = (const float*)d_in[11];
    const float* wi2 = (const float*)d_in[12]; const float* bi2 = (const float*)d_in[13];
    const float* wc2 = (const float*)d_in[14]; const float* bc2 = (const float*)d_in[15];
    const float* wo2 = (const float*)d_in[16]; const float* bo2 = (const float*)d_in[17];
    const float* w_out = (const float*)d_in[18];
    const float* b_out = (const float*)d_in[19];
    float* out = (float*)d_out;

    float *pX, *ph1, *pc1, *ph2, *pc2;
    cudaGetSymbolAddress((void**)&pX,  g_X);
    cudaGetSymbolAddress((void**)&ph1, g_h1);
    cudaGetSymbolAddress((void**)&pc1, g_c1);
    cudaGetSymbolAddress((void**)&ph2, g_h2);
    cudaGetSymbolAddress((void**)&pc2, g_c2);

    {
        int total = TT * BB * EP;
        init_kernel<<<(total + 255) / 256, 256>>>(tokens, emb);
    }

    // Software pipeline: launch k runs layer1(step k) and layer2(step k-1)
    // concurrently — they only depend on state produced by launch k-1.
    // h1(t) lives in buf[(t+1)&1]; h2(t) lives in buf[(t+1)&1].
    dim3 grid(BB / 64, UU / 16, 2);   // 16 x 16 x 2 = 512 CTAs
    for (int k = 0; k <= TT; k++) {
        int do1 = (k < TT) ? 1 : 0;
        int do2 = (k >= 1) ? 1 : 0;
        const float* h1i = ph1 + (k & 1) * HS;          // h1(k-1)
        float*       h1o = ph1 + ((k + 1) & 1) * HS;    // h1(k)
        const float* x1  = pX + (size_t)((k < TT) ? k : 0) * BB * EP;
        const float* h2i = ph2 + ((k + 1) & 1) * HS;    // h2(k-2)
        float*       h2o = ph2 + (k & 1) * HS;          // h2(k-1)
        const float* x2  = ph1 + (k & 1) * HS;          // h1(k-1)
        fused_step<<<grid, 256>>>(
            do1, h1i, h1o, pc1, x1,
            wf1, wi1, wc1, wo1, bf1, bi1, bc1, bo1,
            do2, h2i, h2o, pc2, x2,
            wf2, wi2, wc2, wo2, bf2, bi2, bc2, bo2);
    }

    // final h2 = h2(79) lives in buf[(79+1)&1] = buf[0]
    final_kernel<<<BB / 8, 256>>>(ph2, w_out, b_out, out);
}

// round 5
// speedup vs baseline: 3.6745x; 3.6745x over previous
#include <cuda_runtime.h>
#include <math.h>
#include <stdint.h>

#define BB 1024
#define TT 80
#define EE 100
#define UU 256
#define K1 384          // 256 (h) + 128 (x padded to 128)
#define K2 512          // 256 (h2) + 256 (h1)
#define NTOT 1024       // 4 gates * 256 units (permuted layout, see pack_w)
#define HS (UU*BB)

// ---------------- device scratch ----------------
__device__ float g_XT[(size_t)TT * 128 * BB];    // [t][e][b], e padded to 128, tf32-rounded
__device__ float g_Wp1[(size_t)NTOT * K1];       // [n_packed][k]
__device__ float g_Wp2[(size_t)NTOT * K2];
__device__ float g_h1T[2][HS];                   // [u][b]
__device__ float g_h2T[2][HS];
__device__ float g_c1T[HS];
__device__ float g_c2T[HS];

// ---------------- helpers ----------------
__device__ __forceinline__ float to_tf32(float x) {
    uint32_t u;
    asm("cvt.rna.tf32.f32 %0, %1;" : "=r"(u) : "f"(x));
    return __uint_as_float(u);
}
__device__ __forceinline__ float sigm(float x) {
    return __fdividef(1.0f, 1.0f + __expf(-x));
}
__device__ __forceinline__ float tanh_(float x) {
    return __fdividef(2.0f, 1.0f + __expf(-2.0f * x)) - 1.0f;
}
__device__ __forceinline__ void mma8(float& c0, float& c1, float& c2, float& c3,
                                     uint32_t a0, uint32_t a1, uint32_t a2, uint32_t a3,
                                     uint32_t b0, uint32_t b1) {
    asm volatile(
        "mma.sync.aligned.m16n8k8.row.col.f32.tf32.tf32.f32 "
        "{%0,%1,%2,%3}, {%4,%5,%6,%7}, {%8,%9}, {%0,%1,%2,%3};"
        : "+f"(c0), "+f"(c1), "+f"(c2), "+f"(c3)
        : "r"(a0), "r"(a1), "r"(a2), "r"(a3), "r"(b0), "r"(b1));
}

// ---------------- init kernels ----------------
__global__ void gather_x(const int* __restrict__ tokens, const float* __restrict__ emb) {
    size_t idx = (size_t)blockIdx.x * 256 + threadIdx.x;
    if (idx >= (size_t)TT * 128 * BB) return;
    int b  = idx & (BB - 1);
    int te = (int)(idx >> 10);
    int e  = te & 127;
    int t  = te >> 7;
    float v = 0.0f;
    if (e < EE) v = emb[(size_t)tokens[b * TT + t] * EE + e];
    g_XT[idx] = to_tf32(v);
}

// Packed layout: CTA n-tile = 128 cols = 2 warps x 64. Within a warp's 64 cols:
//   col = j*8 + q*2 + r,  j=0..7, q=0..3, r=0..1
//   unit_local = (j&3)*4 + q,  gate = (j>>2)*2 + r
// so each mma lane (q = lane&3) owns all 4 gates of its units.
__global__ void pack_w(const float* __restrict__ wf1, const float* __restrict__ wi1,
                       const float* __restrict__ wc1, const float* __restrict__ wo1,
                       const float* __restrict__ wf2, const float* __restrict__ wi2,
                       const float* __restrict__ wc2, const float* __restrict__ wo2) {
    int idx = blockIdx.x * 256 + threadIdx.x;
    const int tot1 = NTOT * K1;
    int P, k, KP, which;
    if (idx < tot1) { P = idx / K1; k = idx % K1; KP = K1; which = 1; }
    else if (idx < tot1 + NTOT * K2) {
        int j = idx - tot1; P = j / K2; k = j % K2; KP = K2; which = 2;
    } else return;
    (void)KP;
    int ny  = P >> 7;            // CTA tile (32 units each)
    int rem = P & 127;
    int wn  = rem >> 6;          // warp within CTA (16 units each)
    int col = rem & 63;
    int j = col >> 3, q = (col >> 1) & 3, r = col & 1;
    int u_local = (j & 3) * 4 + q;
    int g = (j >> 2) * 2 + r;
    int u = ny * 32 + wn * 16 + u_local;
    if (which == 1) {
        float v = 0.0f;
        if (k < UU + EE) {
            const float* w = (g == 0) ? wf1 : (g == 1) ? wi1 : (g == 2) ? wc1 : wo1;
            v = w[(size_t)k * UU + u];
        }
        g_Wp1[idx] = to_tf32(v);
    } else {
        const float* w = (g == 0) ? wf2 : (g == 1) ? wi2 : (g == 2) ? wc2 : wo2;
        g_Wp2[(size_t)P * K2 + k] = to_tf32(w[(size_t)k * UU + u]);
    }
}

__global__ void zero_state() {
    int idx = blockIdx.x * 256 + threadIdx.x;
    if (idx < HS) {
        g_h1T[0][idx] = 0.0f;
        g_h2T[0][idx] = 0.0f;
        g_c1T[idx]    = 0.0f;
        g_c2T[idx]    = 0.0f;
    }
}

// ---------------- LSTM tile: 128 batch x 32 units x 4 gates via mma.sync tf32 ----------------
template <int KP>
__device__ __forceinline__ void lstm_tile(
    const float* __restrict__ hT, const float* __restrict__ xT,
    const float* __restrict__ Wp,
    const float* __restrict__ bfv, const float* __restrict__ biv,
    const float* __restrict__ bcv, const float* __restrict__ bov,
    float* __restrict__ hoT, float* __restrict__ cT,
    float (*SA)[136], float (*SB)[36], float (*sBias)[32]) {

    const int tid  = threadIdx.x;
    const int lane = tid & 31, wid = tid >> 5;
    const int wm = wid >> 1, wn = wid & 1;
    const int rr = lane >> 2, kq = lane & 3;
    const int b0 = blockIdx.x * 128;
    const int n0 = blockIdx.y * 128;        // packed-col base
    const int u0 = blockIdx.y * 32;         // unit base

    // stage biases for this CTA's 32 units
    if (tid < 128) {
        int g = tid >> 5, ui = tid & 31;
        const float* bsrc = (g == 0) ? bfv : (g == 1) ? biv : (g == 2) ? bcv : bov;
        sBias[g][ui] = bsrc[u0 + ui];
    }

    constexpr int NC = KP / 32;

    // prefetch indices
    const int akb = tid >> 5, am4 = tid & 31;     // A: k row base, float4 col
    const int bnb = tid >> 3, bk4 = tid & 7;      // B: n row base, float4 col

    float4 pa[4], pb[4];
    auto prefetch = [&](int c) {
        const float* asrc = (c * 32 < UU) ? (hT + (size_t)(c * 32) * BB + b0)
                                          : (xT + (size_t)(c * 32 - UU) * BB + b0);
#pragma unroll
        for (int p = 0; p < 4; ++p)
            pa[p] = *(const float4*)(asrc + (size_t)(akb + 8 * p) * BB + am4 * 4);
        const float* wsrc = Wp + (size_t)(n0 + bnb) * KP + c * 32 + bk4 * 4;
#pragma unroll
        for (int p = 0; p < 4; ++p)
            pb[p] = *(const float4*)(wsrc + (size_t)(32 * p) * KP);
    };

    float acc[2][8][4];
#pragma unroll
    for (int mi = 0; mi < 2; ++mi)
#pragma unroll
        for (int j = 0; j < 8; ++j)
#pragma unroll
            for (int e = 0; e < 4; ++e) acc[mi][j][e] = 0.0f;

    prefetch(0);
    for (int c = 0; c < NC; ++c) {
        if (c > 0) __syncthreads();             // all warps done reading smem
#pragma unroll
        for (int p = 0; p < 4; ++p) *(float4*)&SA[akb + 8 * p][am4 * 4] = pa[p];
#pragma unroll
        for (int p = 0; p < 4; ++p) *(float4*)&SB[bnb + 32 * p][bk4 * 4] = pb[p];
        __syncthreads();
        if (c + 1 < NC) prefetch(c + 1);

#pragma unroll
        for (int ks = 0; ks < 4; ++ks) {
            const int k0 = ks * 8;
            uint32_t a[2][4];
#pragma unroll
            for (int mi = 0; mi < 2; ++mi) {
                const int mb = wm * 32 + mi * 16 + rr;
                a[mi][0] = __float_as_uint(SA[k0 + kq    ][mb    ]);
                a[mi][1] = __float_as_uint(SA[k0 + kq    ][mb + 8]);
                a[mi][2] = __float_as_uint(SA[k0 + kq + 4][mb    ]);
                a[mi][3] = __float_as_uint(SA[k0 + kq + 4][mb + 8]);
            }
#pragma unroll
            for (int j = 0; j < 8; ++j) {
                const int nrow = wn * 64 + j * 8 + rr;
                uint32_t b0r = __float_as_uint(SB[nrow][k0 + kq    ]);
                uint32_t b1r = __float_as_uint(SB[nrow][k0 + kq + 4]);
#pragma unroll
                for (int mi = 0; mi < 2; ++mi)
                    mma8(acc[mi][j][0], acc[mi][j][1], acc[mi][j][2], acc[mi][j][3],
                         a[mi][0], a[mi][1], a[mi][2], a[mi][3], b0r, b1r);
            }
        }
    }

    // ---- epilogue: all 4 gates of each owned unit live in this lane's accs ----
    const int q = lane & 3;
#pragma unroll
    for (int mi = 0; mi < 2; ++mi) {
#pragma unroll
        for (int jl = 0; jl < 4; ++jl) {
            const int u_in = wn * 16 + jl * 4 + q;
            const int u = u0 + u_in;
            const float bf_ = sBias[0][u_in], bi_ = sBias[1][u_in];
            const float bc_ = sBias[2][u_in], bo_ = sBias[3][u_in];
#pragma unroll
            for (int rh = 0; rh < 2; ++rh) {
                const int b = b0 + wm * 32 + mi * 16 + rh * 8 + rr;
                float pf = acc[mi][jl    ][rh * 2 + 0] + bf_;
                float pi = acc[mi][jl    ][rh * 2 + 1] + bi_;
                float pc = acc[mi][jl + 4][rh * 2 + 0] + bc_;
                float po = acc[mi][jl + 4][rh * 2 + 1] + bo_;
                size_t off = (size_t)u * BB + b;
                float cn = sigm(pf) * cT[off] + sigm(pi) * tanh_(pc);
                cT[off]  = cn;
                hoT[off] = to_tf32(sigm(po) * tanh_(cn));
            }
        }
    }
}

// ---------------- fused step kernel: z=0 -> layer2(k-1), z=1 -> layer1(k) ----------------
__global__ __launch_bounds__(256, 1)
void step_kernel(
    int do1, const float* __restrict__ h1i, float* __restrict__ h1o,
    float* __restrict__ c1, const float* __restrict__ x1,
    const float* __restrict__ Wp1,
    const float* __restrict__ bf1, const float* __restrict__ bi1,
    const float* __restrict__ bc1, const float* __restrict__ bo1,
    int do2, const float* __restrict__ h2i, float* __restrict__ h2o,
    float* __restrict__ c2, const float* __restrict__ x2,
    const float* __restrict__ Wp2,
    const float* __restrict__ bf2, const float* __restrict__ bi2,
    const float* __restrict__ bc2, const float* __restrict__ bo2) {

    __shared__ float SA[32][136];
    __shared__ float SB[128][36];
    __shared__ float sBias[4][32];

    if (blockIdx.z == 1) {
        if (!do1) return;
        lstm_tile<K1>(h1i, x1, Wp1, bf1, bi1, bc1, bo1, h1o, c1, SA, SB, sBias);
    } else {
        if (!do2) return;
        lstm_tile<K2>(h2i, x2, Wp2, bf2, bi2, bc2, bo2, h2o, c2, SA, SB, sBias);
    }
}

// ---------------- output head ----------------
__global__ void final_kernel(const float* __restrict__ h2T,
                             const float* __restrict__ w_out,
                             const float* __restrict__ b_out,
                             float* __restrict__ out) {
    int b = blockIdx.x * 256 + threadIdx.x;
    float s = 0.0f;
#pragma unroll 8
    for (int u = 0; u < UU; ++u) s += h2T[(size_t)u * BB + b] * w_out[u];
    out[b] = __fdividef(1.0f, 1.0f + __expf(-(s + b_out[0])));
}

// ---------------- launch ----------------
extern "C" void kernel_launch(void* const* d_in, const int* in_sizes, int n_in,
                              void* d_out, int out_size) {
    const int*   tokens = (const int*)d_in[0];
    const float* emb    = (const float*)d_in[1];
    const float* wf1 = (const float*)d_in[2];  const float* bf1 = (const float*)d_in[3];
    const float* wi1 = (const float*)d_in[4];  const float* bi1 = (const float*)d_in[5];
    const float* wc1 = (const float*)d_in[6];  const float* bc1 = (const float*)d_in[7];
    const float* wo1 = (const float*)d_in[8];  const float* bo1 = (const float*)d_in[9];
    const float* wf2 = (const float*)d_in[10]; const float* bf2 = (const float*)d_in[11];
    const float* wi2 = (const float*)d_in[12]; const float* bi2 = (const float*)d_in[13];
    const float* wc2 = (const float*)d_in[14]; const float* bc2 = (const float*)d_in[15];
    const float* wo2 = (const float*)d_in[16]; const float* bo2 = (const float*)d_in[17];
    const float* w_out = (const float*)d_in[18];
    const float* b_out = (const float*)d_in[19];
    float* out = (float*)d_out;

    float *pXT, *pW1, *pW2, *ph1, *pc1, *ph2, *pc2;
    cudaGetSymbolAddress((void**)&pXT, g_XT);
    cudaGetSymbolAddress((void**)&pW1, g_Wp1);
    cudaGetSymbolAddress((void**)&pW2, g_Wp2);
    cudaGetSymbolAddress((void**)&ph1, g_h1T);
    cudaGetSymbolAddress((void**)&pc1, g_c1T);
    cudaGetSymbolAddress((void**)&ph2, g_h2T);
    cudaGetSymbolAddress((void**)&pc2, g_c2T);

    {
        size_t totx = (size_t)TT * 128 * BB;
        gather_x<<<(unsigned)((totx + 255) / 256), 256>>>(tokens, emb);
        int totw = NTOT * K1 + NTOT * K2;
        pack_w<<<(totw + 255) / 256, 256>>>(wf1, wi1, wc1, wo1, wf2, wi2, wc2, wo2);
        zero_state<<<(HS + 255) / 256, 256>>>();
    }

    // Pipelined schedule: launch k runs layer1(step k) and layer2(step k-1).
    dim3 grid(BB / 128, NTOT / 128, 2);      // 8 x 8 x 2 = 128 CTAs
    for (int k = 0; k <= TT; k++) {
        int do1 = (k < TT) ? 1 : 0;
        int do2 = (k >= 1) ? 1 : 0;
        const float* h1i = ph1 + (k & 1) * HS;          // h1(k-1)
        float*       h1o = ph1 + ((k + 1) & 1) * HS;    // h1(k)
        const float* x1  = pXT + (size_t)((k < TT) ? k : 0) * 128 * BB;
        const float* h2i = ph2 + ((k + 1) & 1) * HS;    // h2(k-2)
        float*       h2o = ph2 + (k & 1) * HS;          // h2(k-1)
        const float* x2  = ph1 + (k & 1) * HS;          // h1(k-1)
        step_kernel<<<grid, 256>>>(
            do1, h1i, h1o, pc1, x1, pW1, bf1, bi1, bc1, bo1,
            do2, h2i, h2o, pc2, x2, pW2, bf2, bi2, bc2, bo2);
    }

    // h2(79) lives in buf[80&1] = buf0
    final_kernel<<<BB / 256, 256>>>(ph2, w_out, b_out, out);
}